// round 9
// baseline (speedup 1.0000x reference)
#include <cuda_runtime.h>
#include <cstdint>

// GCNConv: out = D^-1/2 (A + I) D^-1/2 (x @ W) + b
// R9: fill_csr merged into persistent TF32 GEMM (dynamic tile stealing),
//     ldmatrix A-frags + k+1 software pipelining. 4 launches total.

#define MAX_N 100000
#define MAX_E 1600000
#define C 128
#define SCAN_B 512
#define NB_MAX ((MAX_N + SCAN_B - 1) / SCAN_B)

#define GM 64          // rows per tile
#define SA 132         // x smem row stride (words)
#define SBW 264        // W pair-row stride (words); 264%32==8 -> conflict-free
#define GGRID 296      // one full wave at 2 blocks/SM
#define FILLB 148      // blocks that also fill CSR

__device__ int   g_deg[MAX_N];
__device__ float g_dinv[MAX_N];
__device__ int   g_rowptr[MAX_N + 1];
__device__ int   g_cursor[MAX_N];
__device__ int   g_csrc[MAX_E];
__device__ unsigned long long g_status[NB_MAX];
__device__ int   g_ticket;
__device__ int   g_tile;
__device__ float g_wf[64 * SBW];                  // tf32 W, pair-permuted rows
__device__ float g_h[(size_t)MAX_N * C];          // h' = (xW)*dinv, L2-resident

__device__ __forceinline__ uint32_t f2tf32(float f) {
    uint32_t u;
    asm("cvt.rna.tf32.f32 %0, %1;" : "=r"(u) : "f"(f));
    return u;
}
__device__ __forceinline__ float tf32f(float f) { return __uint_as_float(f2tf32(f)); }

// int64 payload (values < 2^31) has zero high words at odd int32 slots.
__device__ __forceinline__ int detect_is64(const int* __restrict__ ei32) {
    __shared__ int s64;
    if (threadIdx.x == 0) s64 = 1;
    __syncthreads();
    if (threadIdx.x < 256 && ei32[2 * threadIdx.x + 1] != 0) s64 = 0;
    __syncthreads();
    return s64;
}

// ---------------------------------------------------------------------------
// count_deg: in-degree + zero scan aux + rowptr[n]=E + (block 1) tf32-permute W.
// ---------------------------------------------------------------------------
__global__ __launch_bounds__(256) void count_deg(const int* __restrict__ ei32,
                                                 const float* __restrict__ W,
                                                 int E, int n, int NB) {
    int is64 = detect_is64(ei32);
    if (blockIdx.x == 0) {
        if (threadIdx.x == 0) { g_ticket = 0; g_rowptr[n] = E; }
        for (int p = threadIdx.x; p < NB; p += 256) g_status[p] = 0ULL;
    }
    int wblk = (gridDim.x > 1) ? 1 : 0;
    if (blockIdx.x == wblk) {
        for (int idx = threadIdx.x; idx < 64 * 128; idx += 256) {
            int p = idx >> 7, c = idx & 127;
            int k8 = p >> 2, t = p & 3;
            g_wf[p * SBW + 2 * c]     = tf32f(W[(size_t)(k8 * 8 + t) * C + c]);
            g_wf[p * SBW + 2 * c + 1] = tf32f(W[(size_t)(k8 * 8 + t + 4) * C + c]);
        }
    }
    int e0 = (blockIdx.x * 256 + threadIdx.x) * 4;
    if (e0 >= E) return;
    int m = E - e0; if (m > 4) m = 4;
    if (is64) {
        const long long* d = (const long long*)ei32 + (size_t)E + e0;
#pragma unroll
        for (int k = 0; k < 4; k++)
            if (k < m) atomicAdd(&g_deg[(int)d[k]], 1);
    } else {
        const int* d = ei32 + (size_t)E + e0;
#pragma unroll
        for (int k = 0; k < 4; k++)
            if (k < m) atomicAdd(&g_deg[d[k]], 1);
    }
}

// ---------------------------------------------------------------------------
// Single-pass exclusive scan (decoupled lookback, ticket-ordered) + dinv.
// Also resets the GEMM tile counter.
// ---------------------------------------------------------------------------
__global__ __launch_bounds__(SCAN_B) void scan_csr(int n) {
    __shared__ int sh[SCAN_B];
    __shared__ int s_ticket, s_prefix;
    if (threadIdx.x == 0) s_ticket = atomicAdd(&g_ticket, 1);
    __syncthreads();
    const int t = s_ticket;
    const int i = t * SCAN_B + threadIdx.x;
    if (t == 0 && threadIdx.x == 0) g_tile = 0;

    int cnt = (i < n) ? g_deg[i] : 0;
    if (i < n) g_dinv[i] = rsqrtf((float)(cnt + 1));

    sh[threadIdx.x] = cnt;
    __syncthreads();
    for (int off = 1; off < SCAN_B; off <<= 1) {
        int v = (threadIdx.x >= off) ? sh[threadIdx.x - off] : 0;
        __syncthreads();
        sh[threadIdx.x] += v;
        __syncthreads();
    }
    int incl  = sh[threadIdx.x];
    int total = sh[SCAN_B - 1];

    if (threadIdx.x < 32) {
        int lane = threadIdx.x;
        if (lane == 0) {
            if (t == 0) {
                atomicExch(&g_status[0], (2ULL << 62) | (unsigned)total);
                s_prefix = 0;
            } else {
                atomicExch(&g_status[t], (1ULL << 62) | (unsigned)total);
            }
        }
        if (t > 0) {
            long long pref = 0;
            int base = t;
            for (;;) {
                int p = base - 1 - lane;
                int flag = 0, val = 0;
                if (p >= 0) {
                    unsigned long long s;
                    do {
                        s = atomicAdd(&g_status[p], 0ULL);
                        flag = (int)(s >> 62);
                    } while (flag == 0);
                    val = (int)(s & 0xffffffffu);
                }
                unsigned f2 = __ballot_sync(0xffffffffu, p >= 0 && flag == 2);
                int first = f2 ? (__ffs(f2) - 1) : 32;
                int contrib = (p >= 0 && lane <= first) ? val : 0;
#pragma unroll
                for (int off = 16; off; off >>= 1)
                    contrib += __shfl_down_sync(0xffffffffu, contrib, off);
                if (lane == 0) pref += contrib;
                if (f2) break;
                base -= 32;
            }
            if (lane == 0) {
                atomicExch(&g_status[t], (2ULL << 62) | (unsigned)(pref + (long long)total));
                s_prefix = (int)pref;
            }
        }
    }
    __syncthreads();
    if (i < n) {
        int excl = s_prefix + incl - cnt;
        g_rowptr[i] = excl;
        g_cursor[i] = excl;
    }
}

// ---------------------------------------------------------------------------
// Merged GEMM + CSR fill. Blocks 0..FILLB-1 first scatter their edge share,
// all blocks then steal 64-row GEMM tiles via an atomic counter.
// Mainloop per k: 2 LDSM.x4 (A) + 4 LDS.64 (B) + 8 MMA, frags pipelined k+1.
// ---------------------------------------------------------------------------
__global__ __launch_bounds__(256, 2) void gemm_fill(const float* __restrict__ x,
                                                    const int* __restrict__ ei32,
                                                    int E, int n, int ntiles) {
    extern __shared__ float smem[];
    float* xs = smem;              // [GM][SA]
    float* ws = smem + GM * SA;    // [64][SBW] tf32 W pair-rows

    const int tid  = threadIdx.x;
    const int lane = tid & 31;
    const int wid  = tid >> 5;
    const int wm   = wid >> 2;
    const int wn   = wid & 3;
    const int g    = lane >> 2;
    const int t    = lane & 3;
    const int lr   = tid >> 2;     // load row 0..63
    const int lq   = tid & 3;      // load quarter

    int is64 = detect_is64(ei32);

    // Copy pre-permuted tf32 W into smem (once per block)
    {
        const float4* wsrc = (const float4*)g_wf;
        float4* wdst = (float4*)ws;
        for (int i = tid; i < 64 * SBW / 4; i += 256) wdst[i] = wsrc[i];
    }

    // CSR fill share (blocks 0..FILLB-1). GEMM-only blocks steal tiles meanwhile.
    if (blockIdx.x < FILLB) {
        int per = (E + FILLB - 1) / FILLB;
        int eb  = blockIdx.x * per;
        int ee  = eb + per; if (ee > E) ee = E;
        for (int e0 = eb + tid * 4; e0 < ee; e0 += 256 * 4) {
            int m = ee - e0; if (m > 4) m = 4;
#pragma unroll
            for (int k = 0; k < 4; k++) {
                if (k >= m) break;
                int e = e0 + k;
                int src, dst;
                if (is64) {
                    src = (int)((const long long*)ei32)[e];
                    dst = (int)((const long long*)ei32)[(size_t)E + e];
                } else {
                    src = ei32[e];
                    dst = ei32[(size_t)E + e];
                }
                int p = atomicAdd(&g_cursor[dst], 1);
                g_csrc[p] = src;
            }
        }
    }

    // ldmatrix lane addressing for A frags (per ms)
    const uint32_t xs_u32 = (uint32_t)__cvta_generic_to_shared(xs);
    const int lrow = lane & 15;
    const int lcol = (lane >> 4) << 2;
    uint32_t addrA[2];
#pragma unroll
    for (int ms = 0; ms < 2; ms++)
        addrA[ms] = xs_u32 + (((wm * 32 + ms * 16 + lrow) * SA) + lcol) * 4;

    __shared__ int s_tile;

    for (;;) {
        if (tid == 0) s_tile = atomicAdd(&g_tile, 1);
        __syncthreads();                         // publishes s_tile; xs free
        int tile = s_tile;
        if (tile >= ntiles) break;

        {   // load + cvt + store this tile's x
            int grow = tile * GM + lr;
            const float* xp = x + (size_t)grow * C;
            float* sp = xs + lr * SA;
#pragma unroll
            for (int i = 0; i < 8; i++) {
                float4 v = (grow < n) ? *(const float4*)(xp + (lq * 8 + i) * 4)
                                      : make_float4(0.f, 0.f, 0.f, 0.f);
                v.x = tf32f(v.x); v.y = tf32f(v.y);
                v.z = tf32f(v.z); v.w = tf32f(v.w);
                *(float4*)(sp + (lq * 8 + i) * 4) = v;
            }
        }
        __syncthreads();

        float acc[2][4][4];
#pragma unroll
        for (int ms = 0; ms < 2; ms++)
#pragma unroll
            for (int ns = 0; ns < 4; ns++)
#pragma unroll
                for (int j = 0; j < 4; j++) acc[ms][ns][j] = 0.f;

        uint32_t A[2][2][4];
        float2   B[2][4];

        // preload k=0 frags
#pragma unroll
        for (int ms = 0; ms < 2; ms++)
            asm volatile("ldmatrix.sync.aligned.m8n8.x4.shared.b16 "
                         "{%0,%1,%2,%3}, [%4];"
                         : "=r"(A[0][ms][0]), "=r"(A[0][ms][1]),
                           "=r"(A[0][ms][2]), "=r"(A[0][ms][3])
                         : "r"(addrA[ms]));
#pragma unroll
        for (int ns = 0; ns < 4; ns++)
            B[0][ns] = *(const float2*)(ws + t * SBW + 2 * (wn * 32 + ns * 8 + g));

#pragma unroll
        for (int k = 0; k < 16; k++) {
            const int cb = k & 1, nb = cb ^ 1;
            if (k < 15) {
#pragma unroll
                for (int ms = 0; ms < 2; ms++)
                    asm volatile("ldmatrix.sync.aligned.m8n8.x4.shared.b16 "
                                 "{%0,%1,%2,%3}, [%4];"
                                 : "=r"(A[nb][ms][0]), "=r"(A[nb][ms][1]),
                                   "=r"(A[nb][ms][2]), "=r"(A[nb][ms][3])
                                 : "r"(addrA[ms] + (k + 1) * 32));
#pragma unroll
                for (int ns = 0; ns < 4; ns++)
                    B[nb][ns] = *(const float2*)(ws + ((k + 1) * 4 + t) * SBW
                                                 + 2 * (wn * 32 + ns * 8 + g));
            }
#pragma unroll
            for (int ns = 0; ns < 4; ns++) {
                uint32_t b0 = __float_as_uint(B[cb][ns].x);
                uint32_t b1 = __float_as_uint(B[cb][ns].y);
#pragma unroll
                for (int ms = 0; ms < 2; ms++) {
                    asm volatile(
                        "mma.sync.aligned.m16n8k8.row.col.f32.tf32.tf32.f32 "
                        "{%0,%1,%2,%3}, {%4,%5,%6,%7}, {%8,%9}, {%0,%1,%2,%3};"
                        : "+f"(acc[ms][ns][0]), "+f"(acc[ms][ns][1]),
                          "+f"(acc[ms][ns][2]), "+f"(acc[ms][ns][3])
                        : "r"(A[cb][ms][0]), "r"(A[cb][ms][1]),
                          "r"(A[cb][ms][2]), "r"(A[cb][ms][3]),
                          "r"(b0), "r"(b1));
                }
            }
        }

        // Epilogue: scale by dinv[row], store h'
        int row0 = tile * GM;
#pragma unroll
        for (int ms = 0; ms < 2; ms++) {
            int r = row0 + wm * 32 + ms * 16 + g;
            float s0 = (r < n)     ? g_dinv[r]     : 0.f;
            float s1 = (r + 8 < n) ? g_dinv[r + 8] : 0.f;
#pragma unroll
            for (int ns = 0; ns < 4; ns++) {
                int c = wn * 32 + ns * 8 + t * 2;
                if (r < n)
                    *(float2*)(g_h + (size_t)r * C + c) =
                        make_float2(acc[ms][ns][0] * s0, acc[ms][ns][1] * s0);
                if (r + 8 < n)
                    *(float2*)(g_h + (size_t)(r + 8) * C + c) =
                        make_float2(acc[ms][ns][2] * s1, acc[ms][ns][3] * s1);
            }
        }
    }
}

// ---------------------------------------------------------------------------
// Aggregate: one warp per dst. out = dinv[w]*(h'[w] + sum h'[src]) + b.
// ---------------------------------------------------------------------------
__global__ __launch_bounds__(256) void aggregate(const float* __restrict__ b,
                                                 float* __restrict__ out, int n) {
    int w    = (blockIdx.x * blockDim.x + threadIdx.x) >> 5;
    int lane = threadIdx.x & 31;
    if (w >= n) return;

    float di = g_dinv[w];
    int j  = g_rowptr[w];
    int j1 = g_rowptr[w + 1];
    if (lane == 0) g_deg[w] = 0;      // reset counts for next call

    float4 a0 = *(const float4*)(g_h + (size_t)w * C + lane * 4);
    float4 a1 = make_float4(0.f, 0.f, 0.f, 0.f);
    float4 a2 = make_float4(0.f, 0.f, 0.f, 0.f);
    float4 a3 = make_float4(0.f, 0.f, 0.f, 0.f);

    for (; j + 3 < j1; j += 4) {
        int sA = g_csrc[j], sB = g_csrc[j + 1], sC = g_csrc[j + 2], sD = g_csrc[j + 3];
        float4 vA = *(const float4*)(g_h + (size_t)sA * C + lane * 4);
        float4 vB = *(const float4*)(g_h + (size_t)sB * C + lane * 4);
        float4 vC = *(const float4*)(g_h + (size_t)sC * C + lane * 4);
        float4 vD = *(const float4*)(g_h + (size_t)sD * C + lane * 4);
        a0.x += vA.x; a0.y += vA.y; a0.z += vA.z; a0.w += vA.w;
        a1.x += vB.x; a1.y += vB.y; a1.z += vB.z; a1.w += vB.w;
        a2.x += vC.x; a2.y += vC.y; a2.z += vC.z; a2.w += vC.w;
        a3.x += vD.x; a3.y += vD.y; a3.z += vD.z; a3.w += vD.w;
    }
    for (; j < j1; j++) {
        int sA = g_csrc[j];
        float4 vA = *(const float4*)(g_h + (size_t)sA * C + lane * 4);
        a0.x += vA.x; a0.y += vA.y; a0.z += vA.z; a0.w += vA.w;
    }

    float4 bv = *(const float4*)(b + lane * 4);
    float4 o;
    o.x = fmaf(di, a0.x + a1.x + a2.x + a3.x, bv.x);
    o.y = fmaf(di, a0.y + a1.y + a2.y + a3.y, bv.y);
    o.z = fmaf(di, a0.z + a1.z + a2.z + a3.z, bv.z);
    o.w = fmaf(di, a0.w + a1.w + a2.w + a3.w, bv.w);
    *(float4*)(out + (size_t)w * C + lane * 4) = o;
}

// ---------------------------------------------------------------------------
extern "C" void kernel_launch(void* const* d_in, const int* in_sizes, int n_in,
                              void* d_out, int out_size) {
    const float* x  = (const float*)d_in[0];
    const int*   ei = (const int*)d_in[1];
    const float* W  = (const float*)d_in[2];
    const float* b  = (const float*)d_in[3];
    float* out = (float*)d_out;

    int n  = in_sizes[0] / C;
    int E  = in_sizes[1] / 2;
    int NB = (n + SCAN_B - 1) / SCAN_B;
    int EB = (E + 1023) / 1024;
    int ntiles = (n + GM - 1) / GM;

    const int GEMM_SMEM = (GM * SA + 64 * SBW) * (int)sizeof(float);  // 101376 B
    cudaFuncSetAttribute(gemm_fill, cudaFuncAttributeMaxDynamicSharedMemorySize,
                         GEMM_SMEM);

    count_deg<<<EB, 256>>>(ei, W, E, n, NB);
    scan_csr<<<NB, SCAN_B>>>(n);
    gemm_fill<<<GGRID, 256, GEMM_SMEM>>>(x, ei, E, n, ntiles);
    aggregate<<<(n * 32 + 255) / 256, 256>>>(b, out, n);
}

// round 10
// speedup vs baseline: 1.0310x; 1.0310x over previous
#include <cuda_runtime.h>
#include <cuda_fp16.h>
#include <cstdint>

// GCNConv: out = D^-1/2 (A + I) D^-1/2 (x @ W) + b
// R10 = R8 structure (persistent-W TF32 GEMM, separate fill) with ONE change:
//       h' stored fp16 -> aggregate gather traffic halved (LTS-bound kernel).

#define MAX_N 100000
#define MAX_E 1600000
#define C 128
#define SCAN_B 512
#define NB_MAX ((MAX_N + SCAN_B - 1) / SCAN_B)

#define GM 64          // rows per tile
#define SA 132         // x smem row stride (words)
#define SBW 264        // W pair-row stride (words); 264%32==8 -> conflict-free
#define GEMM_GRID_MAX 296

__device__ int    g_deg[MAX_N];
__device__ float  g_dinv[MAX_N];
__device__ int    g_rowptr[MAX_N + 1];
__device__ int    g_cursor[MAX_N];
__device__ int    g_csrc[MAX_E];
__device__ unsigned long long g_status[NB_MAX];
__device__ int    g_ticket;
__device__ float  g_wf[64 * SBW];                  // tf32 W, pair-permuted rows
__device__ __half g_hh[(size_t)MAX_N * C];         // h' = (xW)*dinv in fp16 (25.6MB)

__device__ __forceinline__ uint32_t f2tf32(float f) {
    uint32_t u;
    asm("cvt.rna.tf32.f32 %0, %1;" : "=r"(u) : "f"(f));
    return u;
}
__device__ __forceinline__ float tf32f(float f) { return __uint_as_float(f2tf32(f)); }

// int64 payload (values < 2^31) has zero high words at odd int32 slots.
__device__ __forceinline__ int detect_is64(const int* __restrict__ ei32) {
    __shared__ int s64;
    if (threadIdx.x == 0) s64 = 1;
    __syncthreads();
    if (threadIdx.x < 256 && ei32[2 * threadIdx.x + 1] != 0) s64 = 0;
    __syncthreads();
    return s64;
}

// ---------------------------------------------------------------------------
// count_deg: in-degree + zero scan aux + rowptr[n]=E + (block 1) tf32-permute W.
// ---------------------------------------------------------------------------
__global__ __launch_bounds__(256) void count_deg(const int* __restrict__ ei32,
                                                 const float* __restrict__ W,
                                                 int E, int n, int NB) {
    int is64 = detect_is64(ei32);
    if (blockIdx.x == 0) {
        if (threadIdx.x == 0) { g_ticket = 0; g_rowptr[n] = E; }
        for (int p = threadIdx.x; p < NB; p += 256) g_status[p] = 0ULL;
    }
    int wblk = (gridDim.x > 1) ? 1 : 0;
    if (blockIdx.x == wblk) {
        for (int idx = threadIdx.x; idx < 64 * 128; idx += 256) {
            int p = idx >> 7, c = idx & 127;
            int k8 = p >> 2, t = p & 3;
            g_wf[p * SBW + 2 * c]     = tf32f(W[(size_t)(k8 * 8 + t) * C + c]);
            g_wf[p * SBW + 2 * c + 1] = tf32f(W[(size_t)(k8 * 8 + t + 4) * C + c]);
        }
    }
    int e0 = (blockIdx.x * 256 + threadIdx.x) * 4;
    if (e0 >= E) return;
    int m = E - e0; if (m > 4) m = 4;
    if (is64) {
        const long long* d = (const long long*)ei32 + (size_t)E + e0;
#pragma unroll
        for (int k = 0; k < 4; k++)
            if (k < m) atomicAdd(&g_deg[(int)d[k]], 1);
    } else {
        const int* d = ei32 + (size_t)E + e0;
#pragma unroll
        for (int k = 0; k < 4; k++)
            if (k < m) atomicAdd(&g_deg[d[k]], 1);
    }
}

// ---------------------------------------------------------------------------
// Single-pass exclusive scan (decoupled lookback, ticket-ordered) + dinv.
// ---------------------------------------------------------------------------
__global__ __launch_bounds__(SCAN_B) void scan_csr(int n) {
    __shared__ int sh[SCAN_B];
    __shared__ int s_ticket, s_prefix;
    if (threadIdx.x == 0) s_ticket = atomicAdd(&g_ticket, 1);
    __syncthreads();
    const int t = s_ticket;
    const int i = t * SCAN_B + threadIdx.x;

    int cnt = (i < n) ? g_deg[i] : 0;
    if (i < n) g_dinv[i] = rsqrtf((float)(cnt + 1));

    sh[threadIdx.x] = cnt;
    __syncthreads();
    for (int off = 1; off < SCAN_B; off <<= 1) {
        int v = (threadIdx.x >= off) ? sh[threadIdx.x - off] : 0;
        __syncthreads();
        sh[threadIdx.x] += v;
        __syncthreads();
    }
    int incl  = sh[threadIdx.x];
    int total = sh[SCAN_B - 1];

    if (threadIdx.x < 32) {
        int lane = threadIdx.x;
        if (lane == 0) {
            if (t == 0) {
                atomicExch(&g_status[0], (2ULL << 62) | (unsigned)total);
                s_prefix = 0;
            } else {
                atomicExch(&g_status[t], (1ULL << 62) | (unsigned)total);
            }
        }
        if (t > 0) {
            long long pref = 0;
            int base = t;
            for (;;) {
                int p = base - 1 - lane;
                int flag = 0, val = 0;
                if (p >= 0) {
                    unsigned long long s;
                    do {
                        s = atomicAdd(&g_status[p], 0ULL);
                        flag = (int)(s >> 62);
                    } while (flag == 0);
                    val = (int)(s & 0xffffffffu);
                }
                unsigned f2 = __ballot_sync(0xffffffffu, p >= 0 && flag == 2);
                int first = f2 ? (__ffs(f2) - 1) : 32;
                int contrib = (p >= 0 && lane <= first) ? val : 0;
#pragma unroll
                for (int off = 16; off; off >>= 1)
                    contrib += __shfl_down_sync(0xffffffffu, contrib, off);
                if (lane == 0) pref += contrib;
                if (f2) break;
                base -= 32;
            }
            if (lane == 0) {
                atomicExch(&g_status[t], (2ULL << 62) | (unsigned)(pref + (long long)total));
                s_prefix = (int)pref;
            }
        }
    }
    __syncthreads();
    if (i < n) {
        int excl = s_prefix + incl - cnt;
        g_rowptr[i] = excl;
        g_cursor[i] = excl;
    }
}

// ---------------------------------------------------------------------------
// Fill CSR: csrc[pos] = src grouped by dst. 4 edges per thread.
// ---------------------------------------------------------------------------
__global__ __launch_bounds__(256) void fill_csr(const int* __restrict__ ei32, int E) {
    int is64 = detect_is64(ei32);
    int e0 = (blockIdx.x * 256 + threadIdx.x) * 4;
    if (e0 >= E) return;
    int m = E - e0; if (m > 4) m = 4;
#pragma unroll
    for (int k = 0; k < 4; k++) {
        if (k >= m) break;
        int e = e0 + k;
        int src, dst;
        if (is64) {
            src = (int)((const long long*)ei32)[e];
            dst = (int)((const long long*)ei32)[(size_t)E + e];
        } else {
            src = ei32[e];
            dst = ei32[(size_t)E + e];
        }
        int p = atomicAdd(&g_cursor[dst], 1);
        g_csrc[p] = src;
    }
}

// ---------------------------------------------------------------------------
// Persistent TF32 GEMM: h'[r] = (x@W)[r] * dinv[r], stored fp16.
// (Mainloop identical to R8's measured-51.9us version.)
// ---------------------------------------------------------------------------
__global__ __launch_bounds__(256, 2) void gemm_tf32(const float* __restrict__ x,
                                                    int n, int ntiles) {
    extern __shared__ float smem[];
    float* xs = smem;              // [GM][SA]
    float* ws = smem + GM * SA;    // [64][SBW] pair-rows

    const int tid  = threadIdx.x;
    const int lane = tid & 31;
    const int wid  = tid >> 5;
    const int wm   = wid >> 2;
    const int wn   = wid & 3;
    const int g    = lane >> 2;
    const int t    = lane & 3;
    const int lr   = tid >> 2;
    const int lq   = tid & 3;

    {   // copy pre-permuted tf32 W into smem once
        const float4* wsrc = (const float4*)g_wf;
        float4* wdst = (float4*)ws;
        for (int i = tid; i < 64 * SBW / 4; i += 256) wdst[i] = wsrc[i];
    }

    float4 xr[8];
    int tile = blockIdx.x;
    if (tile < ntiles) {
        int grow = tile * GM + lr;
        const float* xp = x + (size_t)grow * C;
#pragma unroll
        for (int i = 0; i < 8; i++)
            xr[i] = (grow < n) ? *(const float4*)(xp + (lq * 8 + i) * 4)
                               : make_float4(0.f, 0.f, 0.f, 0.f);
    }

    for (; tile < ntiles; tile += gridDim.x) {
        __syncthreads();
        {
            float* sp = xs + lr * SA;
#pragma unroll
            for (int i = 0; i < 8; i++) {
                float4 v = xr[i];
                v.x = tf32f(v.x); v.y = tf32f(v.y);
                v.z = tf32f(v.z); v.w = tf32f(v.w);
                *(float4*)(sp + (lq * 8 + i) * 4) = v;
            }
        }
        __syncthreads();

        int next = tile + gridDim.x;
        if (next < ntiles) {
            int grow = next * GM + lr;
            const float* xp = x + (size_t)grow * C;
#pragma unroll
            for (int i = 0; i < 8; i++)
                xr[i] = (grow < n) ? *(const float4*)(xp + (lq * 8 + i) * 4)
                                   : make_float4(0.f, 0.f, 0.f, 0.f);
        }

        float acc[2][4][4];
#pragma unroll
        for (int ms = 0; ms < 2; ms++)
#pragma unroll
            for (int ns = 0; ns < 4; ns++)
#pragma unroll
                for (int j = 0; j < 4; j++) acc[ms][ns][j] = 0.f;

#pragma unroll
        for (int k = 0; k < 16; k++) {
            uint32_t a[2][4];
#pragma unroll
            for (int ms = 0; ms < 2; ms++) {
                const float* base = xs + (wm * 32 + ms * 16) * SA + k * 8;
                a[ms][0] = __float_as_uint(base[g * SA + t]);
                a[ms][1] = __float_as_uint(base[(g + 8) * SA + t]);
                a[ms][2] = __float_as_uint(base[g * SA + t + 4]);
                a[ms][3] = __float_as_uint(base[(g + 8) * SA + t + 4]);
            }
#pragma unroll
            for (int ns = 0; ns < 4; ns++) {
                float2 bv = *(const float2*)(ws + (k * 4 + t) * SBW
                                             + 2 * (wn * 32 + ns * 8 + g));
                uint32_t b0 = __float_as_uint(bv.x);
                uint32_t b1 = __float_as_uint(bv.y);
#pragma unroll
                for (int ms = 0; ms < 2; ms++) {
                    asm volatile(
                        "mma.sync.aligned.m16n8k8.row.col.f32.tf32.tf32.f32 "
                        "{%0,%1,%2,%3}, {%4,%5,%6,%7}, {%8,%9}, {%0,%1,%2,%3};"
                        : "+f"(acc[ms][ns][0]), "+f"(acc[ms][ns][1]),
                          "+f"(acc[ms][ns][2]), "+f"(acc[ms][ns][3])
                        : "r"(a[ms][0]), "r"(a[ms][1]), "r"(a[ms][2]), "r"(a[ms][3]),
                          "r"(b0), "r"(b1));
                }
            }
        }

        // Epilogue: scale by dinv[row], store h' as fp16
        int row0 = tile * GM;
#pragma unroll
        for (int ms = 0; ms < 2; ms++) {
            int r = row0 + wm * 32 + ms * 16 + g;
            float s0 = (r < n)     ? g_dinv[r]     : 0.f;
            float s1 = (r + 8 < n) ? g_dinv[r + 8] : 0.f;
#pragma unroll
            for (int ns = 0; ns < 4; ns++) {
                int c = wn * 32 + ns * 8 + t * 2;
                if (r < n)
                    *(__half2*)(g_hh + (size_t)r * C + c) =
                        __floats2half2_rn(acc[ms][ns][0] * s0, acc[ms][ns][1] * s0);
                if (r + 8 < n)
                    *(__half2*)(g_hh + (size_t)(r + 8) * C + c) =
                        __floats2half2_rn(acc[ms][ns][2] * s1, acc[ms][ns][3] * s1);
            }
        }
    }
}

// ---------------------------------------------------------------------------
// Aggregate: one warp per dst. out = dinv[w]*(h'[w] + sum h'[src]) + b.
// fp16 gathers (8B/lane/edge), fp32 accumulation, MLP=4.
// ---------------------------------------------------------------------------
__device__ __forceinline__ void acc_row(float4& a, uint2 v) {
    float2 lo = __half22float2(*(__half2*)&v.x);
    float2 hi = __half22float2(*(__half2*)&v.y);
    a.x += lo.x; a.y += lo.y; a.z += hi.x; a.w += hi.y;
}

__global__ __launch_bounds__(256) void aggregate(const float* __restrict__ b,
                                                 float* __restrict__ out, int n) {
    int w    = (blockIdx.x * blockDim.x + threadIdx.x) >> 5;
    int lane = threadIdx.x & 31;
    if (w >= n) return;

    float di = g_dinv[w];
    int j  = g_rowptr[w];
    int j1 = g_rowptr[w + 1];
    if (lane == 0) g_deg[w] = 0;      // reset counts for next call

    const uint2* hbase = (const uint2*)g_hh;   // 4 halves per uint2
    // row r, lane l -> hbase[r*32 + l]
    float4 a0 = make_float4(0.f, 0.f, 0.f, 0.f);
    float4 a1 = make_float4(0.f, 0.f, 0.f, 0.f);
    float4 a2 = make_float4(0.f, 0.f, 0.f, 0.f);
    float4 a3 = make_float4(0.f, 0.f, 0.f, 0.f);
    acc_row(a0, hbase[(size_t)w * 32 + lane]);   // self loop

    for (; j + 3 < j1; j += 4) {
        int sA = g_csrc[j], sB = g_csrc[j + 1], sC = g_csrc[j + 2], sD = g_csrc[j + 3];
        uint2 vA = hbase[(size_t)sA * 32 + lane];
        uint2 vB = hbase[(size_t)sB * 32 + lane];
        uint2 vC = hbase[(size_t)sC * 32 + lane];
        uint2 vD = hbase[(size_t)sD * 32 + lane];
        acc_row(a0, vA); acc_row(a1, vB); acc_row(a2, vC); acc_row(a3, vD);
    }
    for (; j < j1; j++)
        acc_row(a0, hbase[(size_t)g_csrc[j] * 32 + lane]);

    float4 bv = *(const float4*)(b + lane * 4);
    float4 o;
    o.x = fmaf(di, a0.x + a1.x + a2.x + a3.x, bv.x);
    o.y = fmaf(di, a0.y + a1.y + a2.y + a3.y, bv.y);
    o.z = fmaf(di, a0.z + a1.z + a2.z + a3.z, bv.z);
    o.w = fmaf(di, a0.w + a1.w + a2.w + a3.w, bv.w);
    *(float4*)(out + (size_t)w * C + lane * 4) = o;
}

// ---------------------------------------------------------------------------
extern "C" void kernel_launch(void* const* d_in, const int* in_sizes, int n_in,
                              void* d_out, int out_size) {
    const float* x  = (const float*)d_in[0];
    const int*   ei = (const int*)d_in[1];
    const float* W  = (const float*)d_in[2];
    const float* b  = (const float*)d_in[3];
    float* out = (float*)d_out;

    int n  = in_sizes[0] / C;
    int E  = in_sizes[1] / 2;
    int NB = (n + SCAN_B - 1) / SCAN_B;
    int EB = (E + 1023) / 1024;
    int ntiles = (n + GM - 1) / GM;
    int ggrid = ntiles < GEMM_GRID_MAX ? ntiles : GEMM_GRID_MAX;

    const int GEMM_SMEM = (GM * SA + 64 * SBW) * (int)sizeof(float);  // 101376 B
    cudaFuncSetAttribute(gemm_tf32, cudaFuncAttributeMaxDynamicSharedMemorySize,
                         GEMM_SMEM);

    count_deg<<<EB, 256>>>(ei, W, E, n, NB);
    scan_csr<<<NB, SCAN_B>>>(n);
    fill_csr<<<EB, 256>>>(ei, E);
    gemm_tf32<<<ggrid, 256, GEMM_SMEM>>>(x, n, ntiles);
    aggregate<<<(n * 32 + 255) / 256, 256>>>(b, out, n);
}